// round 1
// baseline (speedup 1.0000x reference)
#include <cuda_runtime.h>

// Problem constants
constexpr int B_  = 64;
constexpr int N_  = 5000;
constexpr int C_  = 64;     // C_IN == C_OUT
constexpr int D_  = 10;
constexpr int NCOL = B_ * C_;         // 4096  (columns of Xt / G)
constexpr int XROW = N_ * C_;         // 320000 (stride per batch in x / out)

// Scratch (allowed: __device__ globals, no allocation)
__device__ float g_S [(size_t)N_ * N_];     // 100 MB : support (row-major, n x m)
__device__ float g_Xt[(size_t)N_ * NCOL];   //  82 MB : Xt[m][b*64+c] = x[b][m][c]
__device__ float g_G [(size_t)N_ * NCOL];   //  82 MB : G = S @ Xt

// ---------------------------------------------------------------------------
// Kernel 1: transpose x (B,N,C) -> Xt (N, B*C). Both sides float4-coalesced.
// ---------------------------------------------------------------------------
__global__ void __launch_bounds__(256) transpose_kernel(const float* __restrict__ x) {
    const int m   = blockIdx.x;
    const int tid = threadIdx.x;
#pragma unroll
    for (int it = 0; it < 4; it++) {
        int j  = it * 256 + tid;          // float4 index in the 4096-wide row
        int b  = j >> 4;                  // 16 float4 per batch segment
        int c4 = (j & 15) << 2;
        float4 v = *(const float4*)(x + (size_t)b * XROW + (size_t)m * C_ + c4);
        *(float4*)(g_Xt + (size_t)m * NCOL + b * C_ + c4) = v;
    }
}

// ---------------------------------------------------------------------------
// Kernel 2: support = softmax(relu(E E^T), axis=1). One block per row n.
// Logits live in registers (10 per thread @ 512 threads).
// ---------------------------------------------------------------------------
__global__ void __launch_bounds__(512) support_kernel(const float* __restrict__ E) {
    const int n   = blockIdx.x;
    const int tid = threadIdx.x;
    __shared__ float en[10];
    __shared__ float redm[16];
    __shared__ float reds[16];

    if (tid < 10) en[tid] = E[n * 10 + tid];
    __syncthreads();

    float lg[10];
    float mx = -1e30f;
#pragma unroll
    for (int it = 0; it < 10; it++) {
        int m = it * 512 + tid;
        float v = -1e30f;
        if (m < N_) {
            const float* em = E + m * 10;
            float s = 0.f;
#pragma unroll
            for (int d = 0; d < 10; d++) s += en[d] * __ldg(em + d);
            v = fmaxf(s, 0.f);            // relu
        }
        lg[it] = v;
        mx = fmaxf(mx, v);
    }
    // block max
#pragma unroll
    for (int o = 16; o > 0; o >>= 1) mx = fmaxf(mx, __shfl_xor_sync(0xffffffffu, mx, o));
    if ((tid & 31) == 0) redm[tid >> 5] = mx;
    __syncthreads();
    if (tid < 32) {
        float v = (tid < 16) ? redm[tid] : -1e30f;
#pragma unroll
        for (int o = 8; o > 0; o >>= 1) v = fmaxf(v, __shfl_xor_sync(0xffffffffu, v, o));
        if (tid == 0) redm[0] = v;
    }
    __syncthreads();
    mx = redm[0];

    float sum = 0.f;
#pragma unroll
    for (int it = 0; it < 10; it++) {
        int m = it * 512 + tid;
        if (m < N_) {
            float e = __expf(lg[it] - mx);
            lg[it] = e;
            sum += e;
        }
    }
    // block sum
#pragma unroll
    for (int o = 16; o > 0; o >>= 1) sum += __shfl_xor_sync(0xffffffffu, sum, o);
    if ((tid & 31) == 0) reds[tid >> 5] = sum;
    __syncthreads();
    if (tid < 32) {
        float v = (tid < 16) ? reds[tid] : 0.f;
#pragma unroll
        for (int o = 8; o > 0; o >>= 1) v += __shfl_xor_sync(0xffffffffu, v, o);
        if (tid == 0) reds[0] = v;
    }
    __syncthreads();
    const float inv = 1.f / reds[0];

#pragma unroll
    for (int it = 0; it < 10; it++) {
        int m = it * 512 + tid;
        if (m < N_) g_S[(size_t)n * N_ + m] = lg[it] * inv;
    }
}

// ---------------------------------------------------------------------------
// Kernel 3: G = S @ Xt.  M=5000, N=4096, K=5000, fp32.
// 128x128x8 tiles, 256 threads, 8x8 microtile, double-buffered smem.
// ---------------------------------------------------------------------------
__global__ void __launch_bounds__(256) sgemm_kernel() {
    constexpr int M = N_;
    constexpr int Nn = NCOL;
    constexpr int K = N_;

    __shared__ float As[2][8][128];   // transposed: As[buf][k][m]
    __shared__ float Bs[2][8][128];

    const int tid  = threadIdx.x;
    const int bm   = blockIdx.y * 128;
    const int bnn  = blockIdx.x * 128;
    const int arow = tid >> 1;           // 0..127
    const int acol = (tid & 1) << 2;     // 0 or 4
    const int brow = tid >> 5;           // 0..7
    const int bcol = (tid & 31) << 2;    // 0..124
    const int ty   = (tid >> 4) << 3;    // 0..120 step 8
    const int tx   = (tid & 15) << 3;

    const bool aval = (bm + arow) < M;
    const float* Aptr = g_S  + (size_t)(bm + arow) * K + acol;
    const float* Bptr = g_Xt + (size_t)brow * Nn + bnn + bcol;

    float acc[8][8];
#pragma unroll
    for (int i = 0; i < 8; i++)
#pragma unroll
        for (int j = 0; j < 8; j++) acc[i][j] = 0.f;

    // prologue: tile 0
    float4 a4 = aval ? *(const float4*)Aptr : make_float4(0.f, 0.f, 0.f, 0.f);
    float4 b4 = *(const float4*)Bptr;
    As[0][acol + 0][arow] = a4.x;
    As[0][acol + 1][arow] = a4.y;
    As[0][acol + 2][arow] = a4.z;
    As[0][acol + 3][arow] = a4.w;
    *(float4*)&Bs[0][brow][bcol] = b4;
    __syncthreads();

    int buf = 0;
    constexpr int kIter = K / 8;         // 625
    for (int kt = 1; kt <= kIter; kt++) {
        float4 an, bnx;
        if (kt < kIter) {                 // prefetch next tile into registers
            an  = aval ? *(const float4*)(Aptr + kt * 8) : make_float4(0.f, 0.f, 0.f, 0.f);
            bnx = *(const float4*)(Bptr + (size_t)kt * 8 * Nn);
        }
#pragma unroll
        for (int kk = 0; kk < 8; kk++) {
            float ar[8], br[8];
            *(float4*)&ar[0] = *(const float4*)&As[buf][kk][ty];
            *(float4*)&ar[4] = *(const float4*)&As[buf][kk][ty + 4];
            *(float4*)&br[0] = *(const float4*)&Bs[buf][kk][tx];
            *(float4*)&br[4] = *(const float4*)&Bs[buf][kk][tx + 4];
#pragma unroll
            for (int i = 0; i < 8; i++)
#pragma unroll
                for (int j = 0; j < 8; j++)
                    acc[i][j] += ar[i] * br[j];
        }
        if (kt < kIter) {
            int nb = buf ^ 1;
            As[nb][acol + 0][arow] = an.x;
            As[nb][acol + 1][arow] = an.y;
            As[nb][acol + 2][arow] = an.z;
            As[nb][acol + 3][arow] = an.w;
            *(float4*)&Bs[nb][brow][bcol] = bnx;
            __syncthreads();
            buf = nb;
        }
    }

#pragma unroll
    for (int i = 0; i < 8; i++) {
        int row = bm + ty + i;
        if (row < M) {
            *(float4*)(g_G + (size_t)row * Nn + bnn + tx) =
                make_float4(acc[i][0], acc[i][1], acc[i][2], acc[i][3]);
            *(float4*)(g_G + (size_t)row * Nn + bnn + tx + 4) =
                make_float4(acc[i][4], acc[i][5], acc[i][6], acc[i][7]);
        }
    }
}

// ---------------------------------------------------------------------------
// Kernel 4: epilogue. One block per node n.
//   W{0,1}[i,o] = sum_d E[n,d] * Wp[d,k,i,o]   (in smem)
//   out[b,n,o]  = bias[n,o] + sum_i x[b,n,i]*W0[i,o] + G[n,b*64+i]*W1[i,o]
// x and G rows (16 KB each) stay L1-resident across the 64-deep i-loop.
// ---------------------------------------------------------------------------
__global__ void __launch_bounds__(256) epilogue_kernel(
    const float* __restrict__ x,  const float* __restrict__ E,
    const float* __restrict__ Wp, const float* __restrict__ bp,
    float* __restrict__ out)
{
    const int n   = blockIdx.x;
    const int tid = threadIdx.x;
    __shared__ float W0s[4096];
    __shared__ float W1s[4096];
    __shared__ float biass[64];
    __shared__ float en[10];

    if (tid < 10) en[tid] = E[n * 10 + tid];
    __syncthreads();

    // per-node weights: 8192 entries, contraction over d=10 (Wp is L2-resident)
#pragma unroll
    for (int it = 0; it < 32; it++) {
        int e = it * 256 + tid;
        float v = 0.f;
#pragma unroll
        for (int d = 0; d < 10; d++) v += en[d] * __ldg(Wp + d * 8192 + e);
        if (e < 4096) W0s[e] = v;
        else          W1s[e - 4096] = v;
    }
    if (tid < 64) {
        float v = 0.f;
#pragma unroll
        for (int d = 0; d < 10; d++) v += en[d] * bp[d * 64 + tid];
        biass[tid] = v;
    }
    __syncthreads();

    const int o4 = (tid & 15) << 2;   // 4 consecutive outputs
    const int b0 = tid >> 4;          // 4 batches: b0, b0+16, b0+32, b0+48
    float acc[4][4];
#pragma unroll
    for (int bi = 0; bi < 4; bi++)
#pragma unroll
        for (int j = 0; j < 4; j++) acc[bi][j] = biass[o4 + j];

    const float* gr = g_G + (size_t)n * NCOL;
    const float* xr = x + (size_t)n * C_;

#pragma unroll 4
    for (int i = 0; i < 64; i++) {
        float4 w0 = *(const float4*)&W0s[i * 64 + o4];
        float4 w1 = *(const float4*)&W1s[i * 64 + o4];
#pragma unroll
        for (int bi = 0; bi < 4; bi++) {
            int b = b0 + bi * 16;
            float xa = __ldg(xr + (size_t)b * XROW + i);
            float ga = __ldg(gr + b * C_ + i);
            acc[bi][0] += xa * w0.x + ga * w1.x;
            acc[bi][1] += xa * w0.y + ga * w1.y;
            acc[bi][2] += xa * w0.z + ga * w1.z;
            acc[bi][3] += xa * w0.w + ga * w1.w;
        }
    }

#pragma unroll
    for (int bi = 0; bi < 4; bi++) {
        int b = b0 + bi * 16;
        *(float4*)(out + (size_t)b * XROW + (size_t)n * C_ + o4) =
            make_float4(acc[bi][0], acc[bi][1], acc[bi][2], acc[bi][3]);
    }
}

// ---------------------------------------------------------------------------
extern "C" void kernel_launch(void* const* d_in, const int* in_sizes, int n_in,
                              void* d_out, int out_size) {
    (void)in_sizes; (void)n_in; (void)out_size;
    const float* x  = (const float*)d_in[0];   // (64, 5000, 64)
    const float* E  = (const float*)d_in[1];   // (5000, 10)
    const float* Wp = (const float*)d_in[2];   // (10, 2, 64, 64)
    const float* bp = (const float*)d_in[3];   // (10, 64)
    float* out = (float*)d_out;                // (64, 5000, 64)

    transpose_kernel<<<N_, 256>>>(x);
    support_kernel  <<<N_, 512>>>(E);
    sgemm_kernel    <<<dim3(NCOL / 128, (N_ + 127) / 128), 256>>>();
    epilogue_kernel <<<N_, 256>>>(x, E, Wp, bp, out);
}

// round 3
// speedup vs baseline: 2.4652x; 2.4652x over previous
#include <cuda_runtime.h>
#include <cuda_bf16.h>
#include <cstdint>

// Problem constants
constexpr int B_  = 64;
constexpr int N_  = 5000;
constexpr int C_  = 64;
constexpr int NCOL = B_ * C_;          // 4096
constexpr int XROW = N_ * C_;          // 320000

// GEMM tiling
constexpr int TM = 128;
constexpr int TN = 256;
constexpr int TK = 64;
constexpr int KC = (N_ + TK - 1) / TK;  // 79

// Scratch (device globals; no allocation)
__device__ __align__(1024) __nv_bfloat16 g_Sh[(size_t)N_ * N_];    // 50 MB
__device__ __align__(1024) __nv_bfloat16 g_Sl[(size_t)N_ * N_];    // 50 MB
__device__ __align__(1024) __nv_bfloat16 g_Bh[(size_t)NCOL * N_];  // 41 MB
__device__ __align__(1024) __nv_bfloat16 g_Bl[(size_t)NCOL * N_];  // 41 MB
__device__ __align__(1024) float         g_G [(size_t)N_ * NCOL];  // 82 MB

// ---------------------------------------------------------------------------
// Helpers
// ---------------------------------------------------------------------------
__device__ __forceinline__ uint32_t smem_u32(const void* p) {
    uint32_t a;
    asm("{ .reg .u64 t; cvta.to.shared.u64 t, %1; cvt.u32.u64 %0, t; }" : "=r"(a) : "l"(p));
    return a;
}
__device__ __forceinline__ uint32_t swz(uint32_t b) { return b ^ ((b >> 3) & 0x70); }

__device__ __forceinline__ void cp16(uint32_t dst, const void* src, int src_bytes) {
    asm volatile("cp.async.cg.shared.global [%0], [%1], 16, %2;"
                 :: "r"(dst), "l"(src), "r"(src_bytes) : "memory");
}
__device__ __forceinline__ void ldsm4(uint32_t* r, uint32_t addr) {
    asm volatile("ldmatrix.sync.aligned.m8n8.x4.shared.b16 {%0,%1,%2,%3}, [%4];"
                 : "=r"(r[0]), "=r"(r[1]), "=r"(r[2]), "=r"(r[3]) : "r"(addr));
}
__device__ __forceinline__ void mma16816(float* d, const uint32_t* a, uint32_t b0, uint32_t b1) {
    asm volatile(
        "mma.sync.aligned.m16n8k16.row.col.f32.bf16.bf16.f32 "
        "{%0,%1,%2,%3}, {%4,%5,%6,%7}, {%8,%9}, {%0,%1,%2,%3};"
        : "+f"(d[0]), "+f"(d[1]), "+f"(d[2]), "+f"(d[3])
        : "r"(a[0]), "r"(a[1]), "r"(a[2]), "r"(a[3]), "r"(b0), "r"(b1));
}

// ---------------------------------------------------------------------------
// Kernel 1: support = softmax(relu(E E^T)) -> bf16 hi/lo split
// ---------------------------------------------------------------------------
__global__ void __launch_bounds__(512) support_kernel(const float* __restrict__ E) {
    const int n   = blockIdx.x;
    const int tid = threadIdx.x;
    __shared__ float en[10];
    __shared__ float redm[16];
    __shared__ float reds[16];

    if (tid < 10) en[tid] = E[n * 10 + tid];
    __syncthreads();

    float lg[10];
    float mx = -1e30f;
#pragma unroll
    for (int it = 0; it < 10; it++) {
        int m = it * 512 + tid;
        float v = -1e30f;
        if (m < N_) {
            const float* em = E + m * 10;
            float s = 0.f;
#pragma unroll
            for (int d = 0; d < 10; d++) s += en[d] * __ldg(em + d);
            v = fmaxf(s, 0.f);
        }
        lg[it] = v;
        mx = fmaxf(mx, v);
    }
#pragma unroll
    for (int o = 16; o > 0; o >>= 1) mx = fmaxf(mx, __shfl_xor_sync(0xffffffffu, mx, o));
    if ((tid & 31) == 0) redm[tid >> 5] = mx;
    __syncthreads();
    if (tid < 32) {
        float v = (tid < 16) ? redm[tid] : -1e30f;
#pragma unroll
        for (int o = 8; o > 0; o >>= 1) v = fmaxf(v, __shfl_xor_sync(0xffffffffu, v, o));
        if (tid == 0) redm[0] = v;
    }
    __syncthreads();
    mx = redm[0];

    float sum = 0.f;
#pragma unroll
    for (int it = 0; it < 10; it++) {
        int m = it * 512 + tid;
        if (m < N_) {
            float e = __expf(lg[it] - mx);
            lg[it] = e;
            sum += e;
        }
    }
#pragma unroll
    for (int o = 16; o > 0; o >>= 1) sum += __shfl_xor_sync(0xffffffffu, sum, o);
    if ((tid & 31) == 0) reds[tid >> 5] = sum;
    __syncthreads();
    if (tid < 32) {
        float v = (tid < 16) ? reds[tid] : 0.f;
#pragma unroll
        for (int o = 8; o > 0; o >>= 1) v += __shfl_xor_sync(0xffffffffu, v, o);
        if (tid == 0) reds[0] = v;
    }
    __syncthreads();
    const float inv = 1.f / reds[0];

#pragma unroll
    for (int it = 0; it < 10; it++) {
        int m = it * 512 + tid;
        if (m < N_) {
            float v = lg[it] * inv;
            __nv_bfloat16 hi = __float2bfloat16_rn(v);
            __nv_bfloat16 lo = __float2bfloat16_rn(v - __bfloat162float(hi));
            g_Sh[(size_t)n * N_ + m] = hi;
            g_Sl[(size_t)n * N_ + m] = lo;
        }
    }
}

// ---------------------------------------------------------------------------
// Kernel 2: x (B,N,C) -> Xb (NCOL, N) bf16 hi/lo: Xb[b*64+c][m] = x[b][m][c]
// ---------------------------------------------------------------------------
__global__ void __launch_bounds__(256) convert_kernel(const float* __restrict__ x) {
    __shared__ float tile[64][65];
    const int m0 = blockIdx.x * 64;
    const int b  = blockIdx.y;
    const int tid = threadIdx.x;

#pragma unroll
    for (int p = 0; p < 16; p++) {
        int idx = p * 256 + tid;
        int mi = idx >> 6, c = idx & 63;
        float v = 0.f;
        if (m0 + mi < N_) v = x[(size_t)b * XROW + (size_t)(m0 + mi) * C_ + c];
        tile[mi][c] = v;
    }
    __syncthreads();
#pragma unroll
    for (int p = 0; p < 16; p++) {
        int idx = p * 256 + tid;
        int c = idx >> 6, mi = idx & 63;
        if (m0 + mi < N_) {
            float v = tile[mi][c];
            __nv_bfloat16 hi = __float2bfloat16_rn(v);
            __nv_bfloat16 lo = __float2bfloat16_rn(v - __bfloat162float(hi));
            size_t o = (size_t)(b * 64 + c) * N_ + m0 + mi;
            g_Bh[o] = hi;
            g_Bl[o] = lo;
        }
    }
}

// ---------------------------------------------------------------------------
// Kernel 3: G = S @ Xb^T via mma.sync bf16, 3-term split, fp32 accumulate.
// CTA tile 128x256x64, 256 threads (8 warps, warp tile 64x64),
// 2-stage cp.async double buffer, SW128-swizzled smem, ldmatrix.x4.
// ---------------------------------------------------------------------------
constexpr int SZ_AH = TM * 128;        // 16384 B
constexpr int SZ_B  = TN * 128;        // 32768 B
constexpr int STG_SZ = 2 * SZ_AH + 2 * SZ_B;   // 98304 B
constexpr int GEMM_SMEM = 2 * STG_SZ;          // 196608 B

__device__ __forceinline__ void load_stage(uint32_t st, int k0, int bm, int bn, int tid) {
    const uint32_t sAh = st, sAl = st + SZ_AH;
    const uint32_t sBh = st + 2 * SZ_AH, sBl = st + 2 * SZ_AH + SZ_B;
#pragma unroll
    for (int t = 0; t < 4; t++) {
        int q = t * 256 + tid;             // 1024 granules of 16B
        int row = q >> 3, j = q & 7;
        int gm = bm + row, gk = k0 + j * 8;
        bool v = (gm < N_) && (gk < N_);
        size_t go = v ? ((size_t)gm * N_ + gk) : 0;
        int sz = v ? 16 : 0;
        uint32_t so = swz(row * 128 + j * 16);
        cp16(sAh + so, g_Sh + go, sz);
        cp16(sAl + so, g_Sl + go, sz);
    }
#pragma unroll
    for (int t = 0; t < 8; t++) {
        int q = t * 256 + tid;             // 2048 granules
        int row = q >> 3, j = q & 7;
        int gk = k0 + j * 8;
        bool v = gk < N_;
        size_t go = (size_t)(bn + row) * N_ + (v ? gk : 0);
        int sz = v ? 16 : 0;
        uint32_t so = swz(row * 128 + j * 16);
        cp16(sBh + so, g_Bh + go, sz);
        cp16(sBl + so, g_Bl + go, sz);
    }
}

__global__ void __launch_bounds__(256, 1) gemm_mma_kernel() {
    extern __shared__ char smem[];
    const uint32_t sb = smem_u32(smem);
    const int tid = threadIdx.x, wid = tid >> 5, lid = tid & 31;
    const int bm = blockIdx.y * TM;
    const int bn = blockIdx.x * TN;
    const int wm = wid >> 2;       // 0..1 -> 64 rows each
    const int wn = wid & 3;        // 0..3 -> 64 cols each

    float acc[4][8][4];
#pragma unroll
    for (int mt = 0; mt < 4; mt++)
#pragma unroll
        for (int nt = 0; nt < 8; nt++)
#pragma unroll
            for (int r = 0; r < 4; r++) acc[mt][nt][r] = 0.f;

    const uint32_t st0 = sb, st1 = sb + STG_SZ;

    load_stage(st0, 0, bm, bn, tid);
    asm volatile("cp.async.commit_group;" ::: "memory");

    // Per-lane ldmatrix address components (constant across chunks)
    const int aRow = wm * 64 + (lid & 15);          // + mt*16
    const int aKb  = (lid >> 4) * 16;               // + ks*32
    const int bRow = wn * 64 + ((lid >> 4) & 1) * 8 + (lid & 7);  // + np*16
    const int bKb  = ((lid >> 3) & 1) * 16;         // + ks*32

    for (int i = 0; i < KC; i++) {
        if (i + 1 < KC) load_stage((i & 1) ? st0 : st1, (i + 1) * TK, bm, bn, tid);
        asm volatile("cp.async.commit_group;" ::: "memory");
        asm volatile("cp.async.wait_group 1;" ::: "memory");
        __syncthreads();

        const uint32_t st  = (i & 1) ? st1 : st0;
        const uint32_t sAh = st, sAl = st + SZ_AH;
        const uint32_t sBh = st + 2 * SZ_AH, sBl = st + 2 * SZ_AH + SZ_B;

#pragma unroll
        for (int ks = 0; ks < 4; ks++) {
            uint32_t ah[4][4], al[4][4], bh[4][4], bl[4][4];
#pragma unroll
            for (int mt = 0; mt < 4; mt++) {
                uint32_t off = swz((aRow + mt * 16) * 128 + ks * 32 + aKb);
                ldsm4(ah[mt], sAh + off);
                ldsm4(al[mt], sAl + off);
            }
#pragma unroll
            for (int np = 0; np < 4; np++) {
                uint32_t off = swz((bRow + np * 16) * 128 + ks * 32 + bKb);
                ldsm4(bh[np], sBh + off);
                ldsm4(bl[np], sBl + off);
            }
            // term 1: Ah * Bh
#pragma unroll
            for (int mt = 0; mt < 4; mt++)
#pragma unroll
                for (int nt = 0; nt < 8; nt++) {
                    const uint32_t* b = bh[nt >> 1];
                    mma16816(acc[mt][nt], ah[mt], b[(nt & 1) * 2], b[(nt & 1) * 2 + 1]);
                }
            // term 2: Ah * Bl
#pragma unroll
            for (int mt = 0; mt < 4; mt++)
#pragma unroll
                for (int nt = 0; nt < 8; nt++) {
                    const uint32_t* b = bl[nt >> 1];
                    mma16816(acc[mt][nt], ah[mt], b[(nt & 1) * 2], b[(nt & 1) * 2 + 1]);
                }
            // term 3: Al * Bh
#pragma unroll
            for (int mt = 0; mt < 4; mt++)
#pragma unroll
                for (int nt = 0; nt < 8; nt++) {
                    const uint32_t* b = bh[nt >> 1];
                    mma16816(acc[mt][nt], al[mt], b[(nt & 1) * 2], b[(nt & 1) * 2 + 1]);
                }
        }
        __syncthreads();
    }

    // Store accumulators to g_G (fp32)
    const int rBase = bm + wm * 64 + (lid >> 2);
    const int cBase = bn + wn * 64 + (lid & 3) * 2;
#pragma unroll
    for (int mt = 0; mt < 4; mt++) {
        int r0 = rBase + mt * 16;
        int r1 = r0 + 8;
#pragma unroll
        for (int nt = 0; nt < 8; nt++) {
            int c = cBase + nt * 8;
            if (r0 < N_)
                *(float2*)(g_G + (size_t)r0 * NCOL + c) = make_float2(acc[mt][nt][0], acc[mt][nt][1]);
            if (r1 < N_)
                *(float2*)(g_G + (size_t)r1 * NCOL + c) = make_float2(acc[mt][nt][2], acc[mt][nt][3]);
        }
    }
}

// ---------------------------------------------------------------------------
// Kernel 4: epilogue
// ---------------------------------------------------------------------------
__global__ void __launch_bounds__(256) epilogue_kernel(
    const float* __restrict__ x,  const float* __restrict__ E,
    const float* __restrict__ Wp, const float* __restrict__ bp,
    float* __restrict__ out)
{
    const int n   = blockIdx.x;
    const int tid = threadIdx.x;
    __shared__ float W0s[4096];
    __shared__ float W1s[4096];
    __shared__ float biass[64];
    __shared__ float en[10];

    if (tid < 10) en[tid] = E[n * 10 + tid];
    __syncthreads();

#pragma unroll
    for (int it = 0; it < 32; it++) {
        int e = it * 256 + tid;
        float v = 0.f;
#pragma unroll
        for (int d = 0; d < 10; d++) v += en[d] * __ldg(Wp + d * 8192 + e);
        if (e < 4096) W0s[e] = v;
        else          W1s[e - 4096] = v;
    }
    if (tid < 64) {
        float v = 0.f;
#pragma unroll
        for (int d = 0; d < 10; d++) v += en[d] * bp[d * 64 + tid];
        biass[tid] = v;
    }
    __syncthreads();

    const int o4 = (tid & 15) << 2;
    const int b0 = tid >> 4;
    float acc[4][4];
#pragma unroll
    for (int bi = 0; bi < 4; bi++)
#pragma unroll
        for (int j = 0; j < 4; j++) acc[bi][j] = biass[o4 + j];

    const float* gr = g_G + (size_t)n * NCOL;
    const float* xr = x + (size_t)n * C_;

#pragma unroll 4
    for (int i = 0; i < 64; i++) {
        float4 w0 = *(const float4*)&W0s[i * 64 + o4];
        float4 w1 = *(const float4*)&W1s[i * 64 + o4];
#pragma unroll
        for (int bi = 0; bi < 4; bi++) {
            int b = b0 + bi * 16;
            float xa = __ldg(xr + (size_t)b * XROW + i);
            float ga = __ldg(gr + b * C_ + i);
            acc[bi][0] += xa * w0.x + ga * w1.x;
            acc[bi][1] += xa * w0.y + ga * w1.y;
            acc[bi][2] += xa * w0.z + ga * w1.z;
            acc[bi][3] += xa * w0.w + ga * w1.w;
        }
    }

#pragma unroll
    for (int bi = 0; bi < 4; bi++) {
        int b = b0 + bi * 16;
        *(float4*)(out + (size_t)b * XROW + (size_t)n * C_ + o4) =
            make_float4(acc[bi][0], acc[bi][1], acc[bi][2], acc[bi][3]);
    }
}

// ---------------------------------------------------------------------------
extern "C" void kernel_launch(void* const* d_in, const int* in_sizes, int n_in,
                              void* d_out, int out_size) {
    (void)in_sizes; (void)n_in; (void)out_size;
    const float* x  = (const float*)d_in[0];   // (64, 5000, 64)
    const float* E  = (const float*)d_in[1];   // (5000, 10)
    const float* Wp = (const float*)d_in[2];   // (10, 2, 64, 64)
    const float* bp = (const float*)d_in[3];   // (10, 64)
    float* out = (float*)d_out;                // (64, 5000, 64)

    static bool attr_done = false;
    if (!attr_done) {
        cudaFuncSetAttribute(gemm_mma_kernel, cudaFuncAttributeMaxDynamicSharedMemorySize, GEMM_SMEM);
        attr_done = true;
    }

    support_kernel<<<N_, 512>>>(E);
    convert_kernel<<<dim3((N_ + 63) / 64, B_), 256>>>(x);
    gemm_mma_kernel<<<dim3(NCOL / TN, (N_ + TM - 1) / TM), 256, GEMM_SMEM>>>();
    epilogue_kernel<<<N_, 256>>>(x, E, Wp, bp, out);
}